// round 2
// baseline (speedup 1.0000x reference)
#include <cuda_runtime.h>
#include <math.h>

#define T_ 4
#define B_ 32
#define C_ 384
#define N_ 196
#define H_ 12
#define D_ 32
#define BCN (B_*C_*N_)      /* 2408448 */
#define TBCN (T_*BCN)       /* 9633792 */
#define M3 (3*C_)           /* 1152 */

// ---------------- scratch (device globals; no allocations) ----------------
__device__ float g_y[3*TBCN];          // qkv pre-activations  (~116MB)
__device__ unsigned char g_s[3*TBCN];  // qkv spikes (u8)      (~29MB)
__device__ unsigned char g_satt[TBCN]; // attention spikes     (~9.6MB)
__device__ float g_yp[TBCN];           // proj pre-activation  (~38.5MB)
__device__ float g_w[M3*C_];           // packed [q;k;v] weights
__device__ float g_bninv[4*C_];
__device__ float g_bnshift[4*C_];

// ---------------- prep: pack weights + fold BN ----------------
__global__ void prep_kernel(
    const float* __restrict__ qw, const float* __restrict__ kw, const float* __restrict__ vw,
    const float* __restrict__ qg, const float* __restrict__ qb, const float* __restrict__ qm, const float* __restrict__ qv,
    const float* __restrict__ kg, const float* __restrict__ kb, const float* __restrict__ km, const float* __restrict__ kvv,
    const float* __restrict__ vg, const float* __restrict__ vb, const float* __restrict__ vm, const float* __restrict__ vvv,
    const float* __restrict__ pg, const float* __restrict__ pb, const float* __restrict__ pm, const float* __restrict__ pv,
    const float* __restrict__ pbias)
{
    int idx = blockIdx.x * blockDim.x + threadIdx.x;
    if (idx < M3*C_) {
        int mg = idx / C_;
        int k  = idx - mg*C_;
        int p  = mg / C_;
        int o  = mg - p*C_;
        const float* w = (p==0) ? qw : (p==1) ? kw : vw;
        g_w[idx] = w[o*C_ + k];
    }
    if (idx < 4*C_) {
        int p = idx / C_, c = idx - (idx/C_)*C_;
        const float *G,*Bt,*Mn,*Vr; float bias = 0.f;
        if      (p==0){G=qg;Bt=qb;Mn=qm;Vr=qv;}
        else if (p==1){G=kg;Bt=kb;Mn=km;Vr=kvv;}
        else if (p==2){G=vg;Bt=vb;Mn=vm;Vr=vvv;}
        else          {G=pg;Bt=pb;Mn=pm;Vr=pv; bias=pbias[c];}
        float inv = G[c] / sqrtf(Vr[c] + 1e-5f);
        g_bninv[idx]   = inv;
        g_bnshift[idx] = Bt[c] + (bias - Mn[c]) * inv;
    }
}

// ---------------- GEMM: y = BN(W @ x) for q,k,v (M=1152) ----------------
// tile 64(M) x 98(N) x 16(K); 112 threads; thread tile 8x7
#define BM 64
#define BNN 98
#define BK 16

__global__ void gemm_qkv(const float* __restrict__ X)
{
    __shared__ float Ws[BK][BM];
    __shared__ float Xs[BK][BNN];
    int tid = threadIdx.x;
    int tx = tid % 14;        // n group
    int ty = tid / 14;        // m group (0..7)
    int bz = blockIdx.z;      // t*B + b
    int m0 = blockIdx.y * BM;
    int n0 = blockIdx.x * BNN;
    const float* Xb = X + (size_t)bz * (C_*N_);

    float acc[8][7];
#pragma unroll
    for (int i = 0; i < 8; i++)
#pragma unroll
        for (int j = 0; j < 7; j++) acc[i][j] = 0.f;

    for (int k0 = 0; k0 < C_; k0 += BK) {
        for (int i = tid; i < BM*BK; i += 112) {
            int ml = i >> 4, kk = i & 15;
            Ws[kk][ml] = g_w[(m0+ml)*C_ + k0 + kk];
        }
        for (int i = tid; i < BK*BNN; i += 112) {
            int kk = i / BNN, nl = i - kk*BNN;
            Xs[kk][nl] = Xb[(k0+kk)*N_ + n0 + nl];
        }
        __syncthreads();
#pragma unroll
        for (int kk = 0; kk < BK; kk++) {
            float a[8], bb[7];
#pragma unroll
            for (int i = 0; i < 8; i++) a[i] = Ws[kk][ty + 8*i];
#pragma unroll
            for (int j = 0; j < 7; j++) bb[j] = Xs[kk][tx + 14*j];
#pragma unroll
            for (int i = 0; i < 8; i++)
#pragma unroll
                for (int j = 0; j < 7; j++) acc[i][j] += a[i]*bb[j];
        }
        __syncthreads();
    }

    int t = bz >> 5, b = bz & 31;
#pragma unroll
    for (int i = 0; i < 8; i++) {
        int mg = m0 + ty + 8*i;
        int p  = mg / C_;
        int c  = mg - p*C_;
        float inv = g_bninv[mg], sh = g_bnshift[mg];
        float* out = g_y + (size_t)p*TBCN + (size_t)t*BCN + ((size_t)b*C_ + c)*N_ + n0;
#pragma unroll
        for (int j = 0; j < 7; j++) out[tx + 14*j] = acc[i][j]*inv + sh;
    }
}

// ---------------- GEMM: proj on u8 spikes (M=384) ----------------
__global__ void gemm_proj(const float* __restrict__ Wp)
{
    __shared__ float Ws[BK][BM];
    __shared__ float Xs[BK][BNN];
    int tid = threadIdx.x;
    int tx = tid % 14;
    int ty = tid / 14;
    int bz = blockIdx.z;
    int m0 = blockIdx.y * BM;
    int n0 = blockIdx.x * BNN;
    const unsigned char* Sb = g_satt + (size_t)bz * (C_*N_);

    float acc[8][7];
#pragma unroll
    for (int i = 0; i < 8; i++)
#pragma unroll
        for (int j = 0; j < 7; j++) acc[i][j] = 0.f;

    for (int k0 = 0; k0 < C_; k0 += BK) {
        for (int i = tid; i < BM*BK; i += 112) {
            int ml = i >> 4, kk = i & 15;
            Ws[kk][ml] = Wp[(m0+ml)*C_ + k0 + kk];
        }
        for (int i = tid; i < BK*BNN; i += 112) {
            int kk = i / BNN, nl = i - kk*BNN;
            Xs[kk][nl] = (float)Sb[(k0+kk)*N_ + n0 + nl];
        }
        __syncthreads();
#pragma unroll
        for (int kk = 0; kk < BK; kk++) {
            float a[8], bb[7];
#pragma unroll
            for (int i = 0; i < 8; i++) a[i] = Ws[kk][ty + 8*i];
#pragma unroll
            for (int j = 0; j < 7; j++) bb[j] = Xs[kk][tx + 14*j];
#pragma unroll
            for (int i = 0; i < 8; i++)
#pragma unroll
                for (int j = 0; j < 7; j++) acc[i][j] += a[i]*bb[j];
        }
        __syncthreads();
    }

#pragma unroll
    for (int i = 0; i < 8; i++) {
        int mg = m0 + ty + 8*i;  // channel (M=384)
        float inv = g_bninv[3*C_ + mg], sh = g_bnshift[3*C_ + mg];
        float* out = g_yp + (size_t)bz*(C_*N_) + (size_t)mg*N_ + n0;
#pragma unroll
        for (int j = 0; j < 7; j++) out[tx + 14*j] = acc[i][j]*inv + sh;
    }
}

// ---------------- LIF over t for qkv pre-activations -> u8 spikes ----------------
__global__ void lif_qkv()
{
    int idx = blockIdx.x * blockDim.x + threadIdx.x;
    if (idx >= 3*BCN) return;
    int p = idx / BCN;
    int r = idx - p*BCN;
    size_t base = (size_t)p*TBCN + r;
    float v = 0.f;
#pragma unroll
    for (int t = 0; t < T_; t++) {
        float x = g_y[base + (size_t)t*BCN];
        v = v + (x - v)*0.5f;
        unsigned char s = (v >= 1.0f) ? 1 : 0;
        g_s[base + (size_t)t*BCN] = s;
        if (s) v = 0.f;
    }
}

// ---------------- attention: per (b,h), all t; G-factorized; fused LIF(0.5) ----------------
// y[n,d] = 0.25*( sum_c Q[c,n]*G[c,d] + (1-p[n])*(Q[:,n].K[:,n])*V[d,n] )
// G[c,d] = sum_m K[c,m]*p[m]*V[d,m]
__global__ void attn_kernel(const float* __restrict__ policy)
{
    int h = blockIdx.x;  // 0..11
    int b = blockIdx.y;  // 0..31
    int tid = threadIdx.x; // 256

    __shared__ unsigned char Qs[32*196];
    __shared__ unsigned char Ks[32*196];
    __shared__ unsigned char VTs[196*32];   // transposed: [m][d]
    __shared__ float Gs[32*32];
    __shared__ float ps[196];
    __shared__ float dns[196];

    float vlif[32];
#pragma unroll
    for (int d = 0; d < 32; d++) vlif[d] = 0.f;

    for (int t = 0; t < T_; t++) {
        size_t base = (size_t)t*BCN + ((size_t)b*C_ + h*32)*N_;
        // loads (Q,K,V tiles are 32x196 contiguous)
        for (int i = tid; i < 32*196; i += 256) {
            Qs[i] = g_s[base + i];
            Ks[i] = g_s[(size_t)TBCN + base + i];
            int d = i / 196, m = i - d*196;
            VTs[m*32 + d] = g_s[2*(size_t)TBCN + base + i];
        }
        for (int i = tid; i < 196; i += 256)
            ps[i] = policy[(size_t)(t*B_ + b)*N_ + i];
        __syncthreads();

        // diag term: dns[n] = (1-p[n]) * popcount(Q[:,n]&K[:,n])
        if (tid < 196) {
            int n = tid, dd = 0;
#pragma unroll
            for (int c = 0; c < 32; c++) dd += (int)(Qs[c*196+n] & Ks[c*196+n]);
            dns[n] = (1.0f - ps[n]) * (float)dd;
        }

        // G: thread (c = tid&31, dg = tid>>5) computes G[c][4dg..4dg+3]
        {
            int c = tid & 31, dg = tid >> 5;
            float g0=0.f,g1=0.f,g2=0.f,g3=0.f;
            const unsigned char* Kc = Ks + c*196;
            const unsigned char* Vb = VTs + dg*4;
            for (int m = 0; m < 196; m++) {
                float kp = Kc[m] ? ps[m] : 0.0f;
                uchar4 v4 = *(const uchar4*)(Vb + m*32);
                g0 += v4.x ? kp : 0.0f;
                g1 += v4.y ? kp : 0.0f;
                g2 += v4.z ? kp : 0.0f;
                g3 += v4.w ? kp : 0.0f;
            }
            Gs[c*32 + dg*4 + 0] = g0;
            Gs[c*32 + dg*4 + 1] = g1;
            Gs[c*32 + dg*4 + 2] = g2;
            Gs[c*32 + dg*4 + 3] = g3;
        }
        __syncthreads();

        // Y + fused LIF(0.5): thread n owns all d
        if (tid < 196) {
            int n = tid;
            float acc[32];
#pragma unroll
            for (int d = 0; d < 32; d++) acc[d] = 0.f;
            const unsigned char* Qn = Qs + n;
#pragma unroll
            for (int c = 0; c < 32; c++) {
                float qf = (float)Qn[c*196];
                const float4* Gr = (const float4*)(Gs + c*32);
#pragma unroll
                for (int q4 = 0; q4 < 8; q4++) {
                    float4 g4 = Gr[q4];
                    acc[q4*4+0] += qf * g4.x;
                    acc[q4*4+1] += qf * g4.y;
                    acc[q4*4+2] += qf * g4.z;
                    acc[q4*4+3] += qf * g4.w;
                }
            }
            float dn = dns[n];
            const uchar4* Vn = (const uchar4*)(VTs + n*32);
#pragma unroll
            for (int q4 = 0; q4 < 8; q4++) {
                uchar4 v4 = Vn[q4];
                acc[q4*4+0] += v4.x ? dn : 0.0f;
                acc[q4*4+1] += v4.y ? dn : 0.0f;
                acc[q4*4+2] += v4.z ? dn : 0.0f;
                acc[q4*4+3] += v4.w ? dn : 0.0f;
            }
            size_t obase = (size_t)t*BCN + ((size_t)b*C_ + h*32)*N_ + n;
#pragma unroll
            for (int d = 0; d < 32; d++) {
                float y = 0.25f * acc[d];
                float v = vlif[d];
                v = v + (y - v)*0.5f;
                unsigned char s = (v >= 0.5f) ? 1 : 0;
                g_satt[obase + (size_t)d*N_] = s;
                vlif[d] = s ? 0.f : v;
            }
        }
        __syncthreads();
    }
}

// ---------------- final LIF(1.0) -> fp32 output ----------------
__global__ void lif_final(float* __restrict__ out)
{
    int idx = blockIdx.x * blockDim.x + threadIdx.x;
    if (idx >= BCN) return;
    float v = 0.f;
#pragma unroll
    for (int t = 0; t < T_; t++) {
        float x = g_yp[(size_t)t*BCN + idx];
        v = v + (x - v)*0.5f;
        float s = (v >= 1.0f) ? 1.f : 0.f;
        out[(size_t)t*BCN + idx] = s;
        if (s != 0.f) v = 0.f;
    }
}

// ---------------- launch ----------------
extern "C" void kernel_launch(void* const* d_in, const int* in_sizes, int n_in,
                              void* d_out, int out_size)
{
    const float* x      = (const float*)d_in[0];
    const float* policy = (const float*)d_in[1];
    const float* qw = (const float*)d_in[2];
    const float* qg = (const float*)d_in[3];
    const float* qb = (const float*)d_in[4];
    const float* qm = (const float*)d_in[5];
    const float* qv = (const float*)d_in[6];
    const float* kw = (const float*)d_in[7];
    const float* kg = (const float*)d_in[8];
    const float* kb = (const float*)d_in[9];
    const float* km = (const float*)d_in[10];
    const float* kv = (const float*)d_in[11];
    const float* vw = (const float*)d_in[12];
    const float* vg = (const float*)d_in[13];
    const float* vb = (const float*)d_in[14];
    const float* vm = (const float*)d_in[15];
    const float* vv = (const float*)d_in[16];
    const float* pw = (const float*)d_in[17];
    const float* pg = (const float*)d_in[18];
    const float* pb = (const float*)d_in[19];
    const float* pm = (const float*)d_in[20];
    const float* pv = (const float*)d_in[21];
    const float* pbias = (const float*)d_in[22];

    prep_kernel<<<(M3*C_ + 255)/256, 256>>>(qw,kw,vw, qg,qb,qm,qv, kg,kb,km,kv,
                                            vg,vb,vm,vv, pg,pb,pm,pv, pbias);
    gemm_qkv<<<dim3(2,18,128), 112>>>(x);
    lif_qkv<<<(3*BCN + 255)/256, 256>>>();
    attn_kernel<<<dim3(12,32), 256>>>(policy);
    gemm_proj<<<dim3(2,6,128), 112>>>(pw);
    lif_final<<<(BCN + 255)/256, 256>>>((float*)d_out);
}

// round 5
// speedup vs baseline: 1.4563x; 1.4563x over previous
#include <cuda_runtime.h>
#include <cuda_bf16.h>
#include <math.h>
#include <stdint.h>

#define T_ 4
#define B_ 32
#define C_ 384
#define N_ 196
#define NP 224
#define BCN (B_*C_*N_)
#define TBCN (T_*BCN)
#define M3 (3*C_)

// ---------------- device scratch ----------------
__device__ unsigned char g_s[3*TBCN];                    // qkv spikes u8 [p][t][b][c][n]
__device__ __nv_bfloat16 g_sattb[(size_t)128*NP*C_];     // attn spikes bf16 [tb][n(224)][c]
__device__ __nv_bfloat16 g_wq[3][(size_t)M3*C_];         // qkv weight splits
__device__ __nv_bfloat16 g_wp[3][(size_t)C_*C_];         // proj weight splits
__device__ __nv_bfloat16 g_xs[3][(size_t)128*NP*C_];     // x splits [s][tb*224+n][c]
__device__ float g_bninv[4*C_];
__device__ float g_bnshift[4*C_];

// ---------------- helpers ----------------
__device__ __forceinline__ uint32_t smem_u32(const void* p) {
    uint32_t a;
    asm("{ .reg .u64 t; cvta.to.shared.u64 t, %1; cvt.u32.u64 %0, t; }" : "=r"(a) : "l"(p));
    return a;
}
#define CP16(dst, src) asm volatile("cp.async.cg.shared.global [%0], [%1], 16;" :: "r"(dst), "l"(src))
#define CP_COMMIT()    asm volatile("cp.async.commit_group;" ::: "memory")
#define CP_WAIT0()     asm volatile("cp.async.wait_group 0;" ::: "memory")

__device__ __forceinline__ void ldsm_x4(uint32_t& r0, uint32_t& r1, uint32_t& r2, uint32_t& r3, uint32_t a) {
    asm volatile("ldmatrix.sync.aligned.m8n8.x4.shared.b16 {%0,%1,%2,%3}, [%4];"
        : "=r"(r0),"=r"(r1),"=r"(r2),"=r"(r3) : "r"(a));
}
__device__ __forceinline__ void ldsm_x2(uint32_t& r0, uint32_t& r1, uint32_t a) {
    asm volatile("ldmatrix.sync.aligned.m8n8.x2.shared.b16 {%0,%1}, [%2];"
        : "=r"(r0),"=r"(r1) : "r"(a));
}
__device__ __forceinline__ void mma16816(float* d, const uint32_t* a, uint32_t b0, uint32_t b1) {
    asm volatile("mma.sync.aligned.m16n8k16.row.col.f32.bf16.bf16.f32 "
        "{%0,%1,%2,%3}, {%4,%5,%6,%7}, {%8,%9}, {%0,%1,%2,%3};"
        : "+f"(d[0]),"+f"(d[1]),"+f"(d[2]),"+f"(d[3])
        : "r"(a[0]),"r"(a[1]),"r"(a[2]),"r"(a[3]), "r"(b0),"r"(b1));
}

__device__ __forceinline__ void split3(float x, __nv_bfloat16& h, __nv_bfloat16& m, __nv_bfloat16& l) {
    h = __float2bfloat16(x);
    float r = x - __bfloat162float(h);
    m = __float2bfloat16(r);
    r = r - __bfloat162float(m);
    l = __float2bfloat16(r);
}

// ---------------- prep: weight splits + BN fold ----------------
__global__ void prep_misc(
    const float* __restrict__ qw, const float* __restrict__ kw, const float* __restrict__ vw,
    const float* __restrict__ pw,
    const float* __restrict__ qg, const float* __restrict__ qb, const float* __restrict__ qm, const float* __restrict__ qv,
    const float* __restrict__ kg, const float* __restrict__ kb, const float* __restrict__ km, const float* __restrict__ kvv,
    const float* __restrict__ vg, const float* __restrict__ vb, const float* __restrict__ vm, const float* __restrict__ vvv,
    const float* __restrict__ pg, const float* __restrict__ pb, const float* __restrict__ pm, const float* __restrict__ pv,
    const float* __restrict__ pbias)
{
    int idx = blockIdx.x * blockDim.x + threadIdx.x;
    if (idx < M3*C_) {
        int m = idx / C_, k = idx - m*C_;
        int p = m / C_, o = m - p*C_;
        const float* w = (p==0) ? qw : (p==1) ? kw : vw;
        __nv_bfloat16 h,md,l; split3(w[o*C_ + k], h, md, l);
        g_wq[0][idx] = h; g_wq[1][idx] = md; g_wq[2][idx] = l;
    }
    if (idx < C_*C_) {
        __nv_bfloat16 h,md,l; split3(pw[idx], h, md, l);
        g_wp[0][idx] = h; g_wp[1][idx] = md; g_wp[2][idx] = l;
    }
    if (idx < 4*C_) {
        int p = idx / C_, c = idx - p*C_;
        const float *G,*Bt,*Mn,*Vr; float bias = 0.f;
        if      (p==0){G=qg;Bt=qb;Mn=qm;Vr=qv;}
        else if (p==1){G=kg;Bt=kb;Mn=km;Vr=kvv;}
        else if (p==2){G=vg;Bt=vb;Mn=vm;Vr=vvv;}
        else          {G=pg;Bt=pb;Mn=pm;Vr=pv; bias=pbias[c];}
        float inv = G[c] / sqrtf(Vr[c] + 1e-5f);
        g_bninv[idx]   = inv;
        g_bnshift[idx] = Bt[c] + (bias - Mn[c]) * inv;
    }
}

// x [t,b,c,n] -> g_xs[s][tb*NP+n][c]  (transpose + split; pad rows zeroed)
__global__ void prep_x(const float* __restrict__ x)
{
    __shared__ float tile[32][33];
    int tb = blockIdx.x;
    int c0 = blockIdx.y * 32;
    int n0 = blockIdx.z * 32;
    int tx = threadIdx.x, ty = threadIdx.y;
#pragma unroll
    for (int r = 0; r < 4; r++) {
        int c = c0 + ty + r*8, n = n0 + tx;
        tile[ty + r*8][tx] = (n < N_) ? x[((size_t)tb*C_ + c)*N_ + n] : 0.f;
    }
    __syncthreads();
#pragma unroll
    for (int r = 0; r < 4; r++) {
        int n = n0 + ty + r*8, c = c0 + tx;
        if (n < NP) {
            __nv_bfloat16 h,md,l; split3(tile[tx][ty + r*8], h, md, l);
            size_t o = ((size_t)tb*NP + n)*C_ + c;
            g_xs[0][o] = h; g_xs[1][o] = md; g_xs[2][o] = l;
        }
    }
}

// ---------------- smem layout for MMA GEMMs ----------------
// A buf: [128][72] bf16 = 18432 B each (x2); B buf: [112][72] bf16 = 16128 B each (x2)
#define SA_BYTES 18432
#define SB_BYTES 16128
#define SB_OFF   (2*SA_BYTES)
#define SMEM_MMA (SB_OFF + 2*SB_BYTES)

__device__ __forceinline__ void copyA(uint32_t sdst, const __nv_bfloat16* src, int tid) {
#pragma unroll
    for (int r = 0; r < 4; r++) {
        int idx = tid + r*256;
        int row = idx >> 3, cs = idx & 7;
        CP16(sdst + (uint32_t)(row*144 + cs*16), src + (size_t)row*C_ + cs*8);
    }
}
__device__ __forceinline__ void copyB(uint32_t sdst, const __nv_bfloat16* src, int tid) {
    for (int idx = tid; idx < 896; idx += 256) {
        int row = idx >> 3, cs = idx & 7;
        CP16(sdst + (uint32_t)(row*144 + cs*16), src + (size_t)row*C_ + cs*8);
    }
}

// compute one K=64 chunk: 4 k-steps x (2 A-frags, 7 B-frags, 14 mma)
__device__ __forceinline__ void compute_chunk(
    float d[2][7][4], uint32_t Abase, uint32_t Bbase, int wm, int wn, int lane)
{
    int lr = lane & 15, lc = (lane >> 4) * 16;      // A ldmatrix: col byte offset
    int r8 = lane & 7, hb = ((lane >> 3) & 1) * 16; // B ldmatrix
    uint32_t arow0 = Abase + (uint32_t)((wm*32 + lr)*144) + lc;
    uint32_t brow0 = Bbase + (uint32_t)((wn*56 + r8)*144) + hb;
#pragma unroll
    for (int ks = 0; ks < 4; ks++) {
        uint32_t a[2][4];
#pragma unroll
        for (int mi = 0; mi < 2; mi++)
            ldsm_x4(a[mi][0],a[mi][1],a[mi][2],a[mi][3], arow0 + mi*16*144 + ks*32);
#pragma unroll
        for (int ni = 0; ni < 7; ni++) {
            uint32_t b0, b1;
            ldsm_x2(b0, b1, brow0 + ni*8*144 + ks*32);
            mma16816(d[0][ni], a[0], b0, b1);
            mma16816(d[1][ni], a[1], b0, b1);
        }
    }
}

// ---------------- qkv GEMM + fused LIF (threshold 1.0) -> u8 spikes ----------------
__global__ __launch_bounds__(256, 1) void gemm_qkv_mma()
{
    extern __shared__ char smem[];
    const uint32_t sbase = smem_u32(smem);
    const int tid = threadIdx.x;
    const int lane = tid & 31, wid = tid >> 5;
    const int wm = wid & 3, wn = wid >> 2;
    const int m0 = blockIdx.x * 128;   // 0..8
    const int n0 = blockIdx.y * 112;   // 0..1
    const int b  = blockIdx.z;         // 0..31
    const int p  = m0 / C_, c0 = m0 % C_;

    float inv_r[4], sh_r[4];
#pragma unroll
    for (int q = 0; q < 4; q++) {
        int m = m0 + wm*32 + (q >> 1)*16 + (q & 1)*8 + (lane >> 2);
        inv_r[q] = g_bninv[m]; sh_r[q] = g_bnshift[m];
    }

    float v[2][7][4];
#pragma unroll
    for (int mi=0;mi<2;mi++)
#pragma unroll
        for(int ni=0;ni<7;ni++)
#pragma unroll
            for(int k=0;k<4;k++) v[mi][ni][k]=0.f;

    const int asel[6]  = {0,1,2,0,1,0};
    const int bsel[6]  = {0,0,0,1,1,2};
    const int bload[6] = {1,0,0,1,0,1};
    const int t4 = lane >> 2, l2 = (lane & 3) * 2;

    for (int t = 0; t < T_; t++) {
        const size_t tb = (size_t)t*B_ + b;
        const size_t brow = (tb*NP + (size_t)n0)*C_;

        float d[2][7][4];
#pragma unroll
        for (int mi=0;mi<2;mi++)
#pragma unroll
            for(int ni=0;ni<7;ni++)
#pragma unroll
                for(int k=0;k<4;k++) d[mi][ni][k]=0.f;

        // prologue: chunk 0 (j=0, kc=0)
        copyA(sbase + 0, g_wq[0] + (size_t)m0*C_, tid);
        copyB(sbase + SB_OFF, g_xs[0] + brow, tid);
        CP_COMMIT();
        int bcur = 0;

        for (int i = 0; i < 36; i++) {
            CP_WAIT0();
            __syncthreads();
            if (i + 1 < 36) {
                int j1 = (i+1) % 6, kc1 = (i+1) / 6;
                copyA(sbase + ((i+1)&1)*SA_BYTES,
                      g_wq[asel[j1]] + (size_t)m0*C_ + kc1*64, tid);
                if (bload[j1])
                    copyB(sbase + SB_OFF + ((bcur+1)&1)*SB_BYTES,
                          g_xs[bsel[j1]] + brow + kc1*64, tid);
                CP_COMMIT();
            }
            compute_chunk(d, sbase + (i&1)*SA_BYTES,
                             sbase + SB_OFF + (bcur&1)*SB_BYTES, wm, wn, lane);
            if (i + 1 < 36 && bload[(i+1)%6]) bcur++;
        }

        // epilogue: BN + LIF -> u8 spikes
#pragma unroll
        for (int mi = 0; mi < 2; mi++) {
#pragma unroll
            for (int hf = 0; hf < 2; hf++) {
                int c = c0 + wm*32 + mi*16 + hf*8 + t4;
                float inv = inv_r[mi*2+hf], sh = sh_r[mi*2+hf];
                unsigned char* orow = g_s + (size_t)p*TBCN + (size_t)t*BCN
                                    + ((size_t)b*C_ + c)*N_;
#pragma unroll
                for (int ni = 0; ni < 7; ni++) {
                    int n = n0 + wn*56 + ni*8 + l2;
                    float y0 = d[mi][ni][hf*2+0]*inv + sh;
                    float y1 = d[mi][ni][hf*2+1]*inv + sh;
                    float v0 = v[mi][ni][hf*2+0], v1 = v[mi][ni][hf*2+1];
                    v0 += (y0 - v0)*0.5f; v1 += (y1 - v1)*0.5f;
                    unsigned int s0 = (v0 >= 1.0f) ? 1u : 0u;
                    unsigned int s1 = (v1 >= 1.0f) ? 1u : 0u;
                    v[mi][ni][hf*2+0] = s0 ? 0.f : v0;
                    v[mi][ni][hf*2+1] = s1 ? 0.f : v1;
                    if (n < N_)
                        *(unsigned short*)(orow + n) = (unsigned short)(s0 | (s1 << 8));
                }
            }
        }
    }
}

// ---------------- proj GEMM + fused final LIF (threshold 1.0) -> fp32 out ----------------
__global__ __launch_bounds__(256, 1) void gemm_proj_mma(float* __restrict__ out)
{
    extern __shared__ char smem[];
    const uint32_t sbase = smem_u32(smem);
    const int tid = threadIdx.x;
    const int lane = tid & 31, wid = tid >> 5;
    const int wm = wid & 3, wn = wid >> 2;
    const int m0 = blockIdx.x * 128;   // 0..2
    const int n0 = blockIdx.y * 112;
    const int b  = blockIdx.z;

    float inv_r[4], sh_r[4];
#pragma unroll
    for (int q = 0; q < 4; q++) {
        int c = m0 + wm*32 + (q >> 1)*16 + (q & 1)*8 + (lane >> 2);
        inv_r[q] = g_bninv[3*C_ + c]; sh_r[q] = g_bnshift[3*C_ + c];
    }

    float v[2][7][4];
#pragma unroll
    for (int mi=0;mi<2;mi++)
#pragma unroll
        for(int ni=0;ni<7;ni++)
#pragma unroll
            for(int k=0;k<4;k++) v[mi][ni][k]=0.f;

    const int bload[3] = {1,0,0};
    const int t4 = lane >> 2, l2 = (lane & 3) * 2;

    for (int t = 0; t < T_; t++) {
        const size_t tb = (size_t)t*B_ + b;
        const size_t brow = (tb*NP + (size_t)n0)*C_;

        float d[2][7][4];
#pragma unroll
        for (int mi=0;mi<2;mi++)
#pragma unroll
            for(int ni=0;ni<7;ni++)
#pragma unroll
                for(int k=0;k<4;k++) d[mi][ni][k]=0.f;

        copyA(sbase + 0, g_wp[0] + (size_t)m0*C_, tid);
        copyB(sbase + SB_OFF, g_sattb + brow, tid);
        CP_COMMIT();
        int bcur = 0;

        for (int i = 0; i < 18; i++) {
            CP_WAIT0();
            __syncthreads();
            if (i + 1 < 18) {
                int j1 = (i+1) % 3, kc1 = (i+1) / 3;
                copyA(sbase + ((i+1)&1)*SA_BYTES,
                      g_wp[j1] + (size_t)m0*C_ + kc1*64, tid);
                if (bload[j1])
                    copyB(sbase + SB_OFF + ((bcur+1)&1)*SB_BYTES,
                          g_sattb + brow + kc1*64, tid);
                CP_COMMIT();
            }
            compute_chunk(d, sbase + (i&1)*SA_BYTES,
                             sbase + SB_OFF + (bcur&1)*SB_BYTES, wm, wn, lane);
            if (i + 1 < 18 && bload[(i+1)%3]) bcur++;
        }

#pragma unroll
        for (int mi = 0; mi < 2; mi++) {
#pragma unroll
            for (int hf = 0; hf < 2; hf++) {
                int c = m0 + wm*32 + mi*16 + hf*8 + t4;
                float inv = inv_r[mi*2+hf], sh = sh_r[mi*2+hf];
                float* orow = out + (size_t)t*BCN + ((size_t)b*C_ + c)*N_;
#pragma unroll
                for (int ni = 0; ni < 7; ni++) {
                    int n = n0 + wn*56 + ni*8 + l2;
                    float y0 = d[mi][ni][hf*2+0]*inv + sh;
                    float y1 = d[mi][ni][hf*2+1]*inv + sh;
                    float v0 = v[mi][ni][hf*2+0], v1 = v[mi][ni][hf*2+1];
                    v0 += (y0 - v0)*0.5f; v1 += (y1 - v1)*0.5f;
                    float s0 = (v0 >= 1.0f) ? 1.f : 0.f;
                    float s1 = (v1 >= 1.0f) ? 1.f : 0.f;
                    v[mi][ni][hf*2+0] = (s0 != 0.f) ? 0.f : v0;
                    v[mi][ni][hf*2+1] = (s1 != 0.f) ? 0.f : v1;
                    if (n < N_) {
                        float2 o2; o2.x = s0; o2.y = s1;
                        *(float2*)(orow + n) = o2;
                    }
                }
            }
        }
    }
}

// ---------------- attention (G-factorized, fused LIF 0.5) -> bf16 spikes [tb][n][c] ----------------
__global__ void attn_kernel(const float* __restrict__ policy)
{
    int h = blockIdx.x, b = blockIdx.y;
    int tid = threadIdx.x;

    __shared__ unsigned char Qs[32*196];
    __shared__ unsigned char Ks[32*196];
    __shared__ unsigned char VTs[196*32];
    __shared__ float Gs[32*32];
    __shared__ float ps[196];
    __shared__ float dns[196];

    float vlif[32];
#pragma unroll
    for (int d = 0; d < 32; d++) vlif[d] = 0.f;

    for (int t = 0; t < T_; t++) {
        size_t base = (size_t)t*BCN + ((size_t)b*C_ + h*32)*N_;
        for (int i = tid; i < 32*196; i += 256) {
            Qs[i] = g_s[base + i];
            Ks[i] = g_s[(size_t)TBCN + base + i];
            int d = i / 196, m = i - d*196;
            VTs[m*32 + d] = g_s[2*(size_t)TBCN + base + i];
        }
        for (int i = tid; i < 196; i += 256)
            ps[i] = policy[(size_t)(t*B_ + b)*N_ + i];
        __syncthreads();

        if (tid < 196) {
            int n = tid, dd = 0;
#pragma unroll
            for (int c = 0; c < 32; c++) dd += (int)(Qs[c*196+n] & Ks[c*196+n]);
            dns[n] = (1.0f - ps[n]) * (float)dd;
        }
        {
            int c = tid & 31, dg = tid >> 5;
            float g0=0.f,g1=0.f,g2=0.f,g3=0.f;
            const unsigned char* Kc = Ks + c*196;
            const unsigned char* Vb = VTs + dg*4;
            for (int m = 0; m < 196; m++) {
                float kp = Kc[m] ? ps[m] : 0.0f;
                uchar4 v4 = *(const uchar4*)(Vb + m*32);
                g0 += v4.x ? kp : 0.0f;
                g1 += v4.y ? kp : 0.0f;
                g2 += v4.z ? kp : 0.0f;
                g3 += v4.w ? kp : 0.0f;
            }
            Gs[c*32 + dg*4 + 0] = g0;
            Gs[c*32 + dg*4 + 1] = g1;
            Gs[c*32 + dg*4 + 2] = g2;
            Gs[c*32 + dg*4 + 3] = g3;
        }
        __syncthreads();

        if (tid < 196) {
            int n = tid;
            float acc[32];
#pragma unroll
            for (int d = 0; d < 32; d++) acc[d] = 0.f;
            const unsigned char* Qn = Qs + n;
#pragma unroll
            for (int c = 0; c < 32; c++) {
                float qf = (float)Qn[c*196];
                const float4* Gr = (const float4*)(Gs + c*32);
#pragma unroll
                for (int q4 = 0; q4 < 8; q4++) {
                    float4 g4 = Gr[q4];
                    acc[q4*4+0] += qf * g4.x;
                    acc[q4*4+1] += qf * g4.y;
                    acc[q4*4+2] += qf * g4.z;
                    acc[q4*4+3] += qf * g4.w;
                }
            }
            float dn = dns[n];
            const uchar4* Vn = (const uchar4*)(VTs + n*32);
#pragma unroll
            for (int q4 = 0; q4 < 8; q4++) {
                uchar4 v4 = Vn[q4];
                acc[q4*4+0] += v4.x ? dn : 0.0f;
                acc[q4*4+1] += v4.y ? dn : 0.0f;
                acc[q4*4+2] += v4.z ? dn : 0.0f;
                acc[q4*4+3] += v4.w ? dn : 0.0f;
            }
            __nv_bfloat16* orow = g_sattb + ((size_t)(t*B_ + b)*NP + n)*C_ + h*32;
#pragma unroll
            for (int d = 0; d < 32; d++) {
                float y = 0.25f * acc[d];
                float v = vlif[d];
                v = v + (y - v)*0.5f;
                unsigned char s = (v >= 0.5f) ? 1 : 0;
                orow[d] = __float2bfloat16(s ? 1.0f : 0.0f);
                vlif[d] = s ? 0.f : v;
            }
        } else if (tid < 196 + (NP - N_)) {
            int n = 196 + (tid - 196);
            __nv_bfloat16* orow = g_sattb + ((size_t)(t*B_ + b)*NP + n)*C_ + h*32;
            __nv_bfloat16 z = __float2bfloat16(0.f);
#pragma unroll
            for (int d = 0; d < 32; d++) orow[d] = z;
        }
        __syncthreads();
    }
}

// ---------------- launch ----------------
extern "C" void kernel_launch(void* const* d_in, const int* in_sizes, int n_in,
                              void* d_out, int out_size)
{
    const float* x      = (const float*)d_in[0];
    const float* policy = (const float*)d_in[1];
    const float* qw = (const float*)d_in[2];
    const float* qg = (const float*)d_in[3];
    const float* qb = (const float*)d_in[4];
    const float* qm = (const float*)d_in[5];
    const float* qv = (const float*)d_in[6];
    const float* kw = (const float*)d_in[7];
    const float* kg = (const float*)d_in[8];
    const float* kb = (const float*)d_in[9];
    const float* km = (const float*)d_in[10];
    const float* kv = (const float*)d_in[11];
    const float* vw = (const float*)d_in[12];
    const float* vg = (const float*)d_in[13];
    const float* vb = (const float*)d_in[14];
    const float* vm = (const float*)d_in[15];
    const float* vv = (const float*)d_in[16];
    const float* pw = (const float*)d_in[17];
    const float* pg = (const float*)d_in[18];
    const float* pb = (const float*)d_in[19];
    const float* pm = (const float*)d_in[20];
    const float* pv = (const float*)d_in[21];
    const float* pbias = (const float*)d_in[22];

    cudaFuncSetAttribute(gemm_qkv_mma, cudaFuncAttributeMaxDynamicSharedMemorySize, SMEM_MMA);
    cudaFuncSetAttribute(gemm_proj_mma, cudaFuncAttributeMaxDynamicSharedMemorySize, SMEM_MMA);

    prep_misc<<<(M3*C_ + 255)/256, 256>>>(qw,kw,vw, pw, qg,qb,qm,qv, kg,kb,km,kv,
                                          vg,vb,vm,vv, pg,pb,pm,pv, pbias);
    prep_x<<<dim3(128, 12, 7), dim3(32, 8)>>>(x);
    gemm_qkv_mma<<<dim3(9, 2, 32), 256, SMEM_MMA>>>();
    attn_kernel<<<dim3(12, 32), 256>>>(policy);
    gemm_proj_mma<<<dim3(3, 2, 32), 256, SMEM_MMA>>>((float*)d_out);
}

// round 6
// speedup vs baseline: 1.6155x; 1.1094x over previous
#include <cuda_runtime.h>
#include <cuda_bf16.h>
#include <math.h>
#include <stdint.h>

#define T_ 4
#define B_ 32
#define C_ 384
#define N_ 196
#define NP 224
#define BCN (B_*C_*N_)
#define TBCN (T_*BCN)
#define M3 (3*C_)

// ---------------- device scratch ----------------
__device__ unsigned char g_s[3*TBCN];                    // qkv spikes u8 [p][t][b][c][n]
__device__ __nv_bfloat16 g_sattb[(size_t)128*NP*C_];     // attn spikes bf16 [tb][n(224)][c]
__device__ __nv_bfloat16 g_wq[3][(size_t)M3*C_];         // qkv weight splits
__device__ __nv_bfloat16 g_wp[3][(size_t)C_*C_];         // proj weight splits
__device__ __nv_bfloat16 g_xs[3][(size_t)128*NP*C_];     // x splits [s][tb*224+n][c]
__device__ float g_bninv[4*C_];
__device__ float g_bnshift[4*C_];

// ---------------- helpers ----------------
__device__ __forceinline__ uint32_t smem_u32(const void* p) {
    uint32_t a;
    asm("{ .reg .u64 t; cvta.to.shared.u64 t, %1; cvt.u32.u64 %0, t; }" : "=r"(a) : "l"(p));
    return a;
}
#define CP16(dst, src) asm volatile("cp.async.cg.shared.global [%0], [%1], 16;" :: "r"(dst), "l"(src))
#define CP_COMMIT()    asm volatile("cp.async.commit_group;" ::: "memory")
#define CP_WAIT0()     asm volatile("cp.async.wait_group 0;" ::: "memory")

__device__ __forceinline__ void ldsm_x4(uint32_t& r0, uint32_t& r1, uint32_t& r2, uint32_t& r3, uint32_t a) {
    asm volatile("ldmatrix.sync.aligned.m8n8.x4.shared.b16 {%0,%1,%2,%3}, [%4];"
        : "=r"(r0),"=r"(r1),"=r"(r2),"=r"(r3) : "r"(a));
}
__device__ __forceinline__ void ldsm_x2(uint32_t& r0, uint32_t& r1, uint32_t a) {
    asm volatile("ldmatrix.sync.aligned.m8n8.x2.shared.b16 {%0,%1}, [%2];"
        : "=r"(r0),"=r"(r1) : "r"(a));
}
__device__ __forceinline__ void mma16816(float* d, const uint32_t* a, uint32_t b0, uint32_t b1) {
    asm volatile("mma.sync.aligned.m16n8k16.row.col.f32.bf16.bf16.f32 "
        "{%0,%1,%2,%3}, {%4,%5,%6,%7}, {%8,%9}, {%0,%1,%2,%3};"
        : "+f"(d[0]),"+f"(d[1]),"+f"(d[2]),"+f"(d[3])
        : "r"(a[0]),"r"(a[1]),"r"(a[2]),"r"(a[3]), "r"(b0),"r"(b1));
}

__device__ __forceinline__ void split3(float x, __nv_bfloat16& h, __nv_bfloat16& m, __nv_bfloat16& l) {
    h = __float2bfloat16(x);
    float r = x - __bfloat162float(h);
    m = __float2bfloat16(r);
    r = r - __bfloat162float(m);
    l = __float2bfloat16(r);
}

// ---------------- prep: weight splits + BN fold ----------------
__global__ void prep_misc(
    const float* __restrict__ qw, const float* __restrict__ kw, const float* __restrict__ vw,
    const float* __restrict__ pw,
    const float* __restrict__ qg, const float* __restrict__ qb, const float* __restrict__ qm, const float* __restrict__ qv,
    const float* __restrict__ kg, const float* __restrict__ kb, const float* __restrict__ km, const float* __restrict__ kvv,
    const float* __restrict__ vg, const float* __restrict__ vb, const float* __restrict__ vm, const float* __restrict__ vvv,
    const float* __restrict__ pg, const float* __restrict__ pb, const float* __restrict__ pm, const float* __restrict__ pv,
    const float* __restrict__ pbias)
{
    int idx = blockIdx.x * blockDim.x + threadIdx.x;
    if (idx < M3*C_) {
        int m = idx / C_, k = idx - m*C_;
        int p = m / C_, o = m - p*C_;
        const float* w = (p==0) ? qw : (p==1) ? kw : vw;
        __nv_bfloat16 h,md,l; split3(w[o*C_ + k], h, md, l);
        g_wq[0][idx] = h; g_wq[1][idx] = md; g_wq[2][idx] = l;
    }
    if (idx < C_*C_) {
        __nv_bfloat16 h,md,l; split3(pw[idx], h, md, l);
        g_wp[0][idx] = h; g_wp[1][idx] = md; g_wp[2][idx] = l;
    }
    if (idx < 4*C_) {
        int p = idx / C_, c = idx - p*C_;
        const float *G,*Bt,*Mn,*Vr; float bias = 0.f;
        if      (p==0){G=qg;Bt=qb;Mn=qm;Vr=qv;}
        else if (p==1){G=kg;Bt=kb;Mn=km;Vr=kvv;}
        else if (p==2){G=vg;Bt=vb;Mn=vm;Vr=vvv;}
        else          {G=pg;Bt=pb;Mn=pm;Vr=pv; bias=pbias[c];}
        float inv = G[c] / sqrtf(Vr[c] + 1e-5f);
        g_bninv[idx]   = inv;
        g_bnshift[idx] = Bt[c] + (bias - Mn[c]) * inv;
    }
}

// x [t,b,c,n] -> g_xs[s][tb*NP+n][c]  (transpose + split; pad rows zeroed)
__global__ void prep_x(const float* __restrict__ x)
{
    __shared__ float tile[32][33];
    int tb = blockIdx.x;
    int c0 = blockIdx.y * 32;
    int n0 = blockIdx.z * 32;
    int tx = threadIdx.x, ty = threadIdx.y;
#pragma unroll
    for (int r = 0; r < 4; r++) {
        int c = c0 + ty + r*8, n = n0 + tx;
        tile[ty + r*8][tx] = (n < N_) ? x[((size_t)tb*C_ + c)*N_ + n] : 0.f;
    }
    __syncthreads();
#pragma unroll
    for (int r = 0; r < 4; r++) {
        int n = n0 + ty + r*8, c = c0 + tx;
        if (n < NP) {
            __nv_bfloat16 h,md,l; split3(tile[tx][ty + r*8], h, md, l);
            size_t o = ((size_t)tb*NP + n)*C_ + c;
            g_xs[0][o] = h; g_xs[1][o] = md; g_xs[2][o] = l;
        }
    }
}

// ---------------- smem layouts ----------------
#define SA_BYTES 18432              /* 128 rows x 144 B */
#define SB224    32256              /* 224 rows x 144 B */
#define SB112    16128              /* 112 rows x 144 B */
#define QKV_SBOFF (2*SA_BYTES)                  /* 36864 */
#define QKV_SMV   (QKV_SBOFF + 2*SB224)         /* 101376 */
#define SMEM_QKV  (QKV_SMV + 128*228*4)         /* 218112 */
#define PROJ_SBOFF (2*SA_BYTES)
#define SMEM_PROJ  (PROJ_SBOFF + 2*SB112)       /* 69120 */

__device__ __forceinline__ void copy_tile(uint32_t sdst, const __nv_bfloat16* src,
                                          int tid, int nthreads, int total) {
    for (int idx = tid; idx < total; idx += nthreads) {
        int row = idx >> 3, cs = idx & 7;
        CP16(sdst + (uint32_t)(row*144 + cs*16), src + (size_t)row*C_ + cs*8);
    }
}

// compute one K=64 chunk: 4 k-steps x (2 A-frags, 7 B-frags, 14 mma)
__device__ __forceinline__ void compute_chunk(
    float d[2][7][4], uint32_t Abase, uint32_t Bbase, int wm, int wn, int lane)
{
    int lr = lane & 15, lc = (lane >> 4) * 16;
    int r8 = lane & 7, hb = ((lane >> 3) & 1) * 16;
    uint32_t arow0 = Abase + (uint32_t)((wm*32 + lr)*144) + lc;
    uint32_t brow0 = Bbase + (uint32_t)((wn*56 + r8)*144) + hb;
#pragma unroll
    for (int ks = 0; ks < 4; ks++) {
        uint32_t a[2][4];
#pragma unroll
        for (int mi = 0; mi < 2; mi++)
            ldsm_x4(a[mi][0],a[mi][1],a[mi][2],a[mi][3], arow0 + mi*16*144 + ks*32);
#pragma unroll
        for (int ni = 0; ni < 7; ni++) {
            uint32_t b0, b1;
            ldsm_x2(b0, b1, brow0 + ni*8*144 + ks*32);
            mma16816(d[0][ni], a[0], b0, b1);
            mma16816(d[1][ni], a[1], b0, b1);
        }
    }
}

// ---------------- qkv GEMM (128x224 tile, 512 thr) + fused LIF -> u8 spikes ----------------
__global__ __launch_bounds__(512, 1) void gemm_qkv_mma()
{
    extern __shared__ char smem[];
    const uint32_t sbase = smem_u32(smem);
    const int tid = threadIdx.x;
    const int lane = tid & 31, wid = tid >> 5;
    const int wm = wid & 3, wn = wid >> 2;   // 4x4 warp grid
    const int m0 = blockIdx.x * 128;         // 0..8
    const int b  = blockIdx.y;               // 0..31
    const int p  = m0 / C_, c0 = m0 % C_;

    float* vsm = (float*)(smem + QKV_SMV);
    for (int i = tid; i < 128*228; i += 512) vsm[i] = 0.f;
    __syncthreads();

    const int asel[6]  = {0,1,2,0,1,0};
    const int bsel[6]  = {0,0,0,1,1,2};
    const int bload[6] = {1,0,0,1,0,1};
    const int t4 = lane >> 2, l2 = (lane & 3) * 2;

    for (int t = 0; t < T_; t++) {
        const size_t brow = ((size_t)(t*B_ + b)*NP)*C_;

        float d[2][7][4];
#pragma unroll
        for (int mi=0;mi<2;mi++)
#pragma unroll
            for(int ni=0;ni<7;ni++)
#pragma unroll
                for(int k=0;k<4;k++) d[mi][ni][k]=0.f;

        copy_tile(sbase + 0, g_wq[0] + (size_t)m0*C_, tid, 512, 1024);
        copy_tile(sbase + QKV_SBOFF, g_xs[0] + brow, tid, 512, 1792);
        CP_COMMIT();
        int bcur = 0;

        for (int i = 0; i < 36; i++) {
            CP_WAIT0();
            __syncthreads();
            if (i + 1 < 36) {
                int j1 = (i+1) % 6, kc1 = (i+1) / 6;
                copy_tile(sbase + ((i+1)&1)*SA_BYTES,
                          g_wq[asel[j1]] + (size_t)m0*C_ + kc1*64, tid, 512, 1024);
                if (bload[j1])
                    copy_tile(sbase + QKV_SBOFF + ((bcur+1)&1)*SB224,
                              g_xs[bsel[j1]] + brow + kc1*64, tid, 512, 1792);
                CP_COMMIT();
            }
            compute_chunk(d, sbase + (i&1)*SA_BYTES,
                             sbase + QKV_SBOFF + (bcur&1)*SB224, wm, wn, lane);
            if (i + 1 < 36 && bload[(i+1)%6]) bcur++;
        }

        // epilogue: BN + LIF (state in smem) -> u8 spikes
#pragma unroll
        for (int mi = 0; mi < 2; mi++) {
#pragma unroll
            for (int hf = 0; hf < 2; hf++) {
                int row = wm*32 + mi*16 + hf*8 + t4;
                int m = m0 + row;
                float inv = g_bninv[m], sh = g_bnshift[m];
                unsigned char* orow = g_s + (size_t)p*TBCN + (size_t)t*BCN
                                    + ((size_t)b*C_ + (c0 + row))*N_;
                float* vrow = vsm + row*228;
#pragma unroll
                for (int ni = 0; ni < 7; ni++) {
                    int n = wn*56 + ni*8 + l2;
                    float y0 = d[mi][ni][hf*2+0]*inv + sh;
                    float y1 = d[mi][ni][hf*2+1]*inv + sh;
                    float v0 = vrow[n], v1 = vrow[n+1];
                    v0 += (y0 - v0)*0.5f; v1 += (y1 - v1)*0.5f;
                    unsigned int s0 = (v0 >= 1.0f) ? 1u : 0u;
                    unsigned int s1 = (v1 >= 1.0f) ? 1u : 0u;
                    vrow[n]   = s0 ? 0.f : v0;
                    vrow[n+1] = s1 ? 0.f : v1;
                    if (n < N_)
                        *(unsigned short*)(orow + n) = (unsigned short)(s0 | (s1 << 8));
                }
            }
        }
        __syncthreads();
    }
}

// ---------------- proj GEMM (128x112 tile, 256 thr) + fused final LIF -> fp32 out ----------------
__global__ __launch_bounds__(256, 1) void gemm_proj_mma(float* __restrict__ out)
{
    extern __shared__ char smem[];
    const uint32_t sbase = smem_u32(smem);
    const int tid = threadIdx.x;
    const int lane = tid & 31, wid = tid >> 5;
    const int wm = wid & 3, wn = wid >> 2;
    const int m0 = blockIdx.x * 128;
    const int n0 = blockIdx.y * 112;
    const int b  = blockIdx.z;

    float inv_r[4], sh_r[4];
#pragma unroll
    for (int q = 0; q < 4; q++) {
        int c = m0 + wm*32 + (q >> 1)*16 + (q & 1)*8 + (lane >> 2);
        inv_r[q] = g_bninv[3*C_ + c]; sh_r[q] = g_bnshift[3*C_ + c];
    }

    float v[2][7][4];
#pragma unroll
    for (int mi=0;mi<2;mi++)
#pragma unroll
        for(int ni=0;ni<7;ni++)
#pragma unroll
            for(int k=0;k<4;k++) v[mi][ni][k]=0.f;

    const int bload[3] = {1,0,0};
    const int t4 = lane >> 2, l2 = (lane & 3) * 2;

    for (int t = 0; t < T_; t++) {
        const size_t brow = (((size_t)(t*B_ + b))*NP + (size_t)n0)*C_;

        float d[2][7][4];
#pragma unroll
        for (int mi=0;mi<2;mi++)
#pragma unroll
            for(int ni=0;ni<7;ni++)
#pragma unroll
                for(int k=0;k<4;k++) d[mi][ni][k]=0.f;

        copy_tile(sbase + 0, g_wp[0] + (size_t)m0*C_, tid, 256, 1024);
        copy_tile(sbase + PROJ_SBOFF, g_sattb + brow, tid, 256, 896);
        CP_COMMIT();
        int bcur = 0;

        for (int i = 0; i < 18; i++) {
            CP_WAIT0();
            __syncthreads();
            if (i + 1 < 18) {
                int j1 = (i+1) % 3, kc1 = (i+1) / 3;
                copy_tile(sbase + ((i+1)&1)*SA_BYTES,
                          g_wp[j1] + (size_t)m0*C_ + kc1*64, tid, 256, 1024);
                if (bload[j1])
                    copy_tile(sbase + PROJ_SBOFF + ((bcur+1)&1)*SB112,
                              g_sattb + brow + kc1*64, tid, 256, 896);
                CP_COMMIT();
            }
            compute_chunk(d, sbase + (i&1)*SA_BYTES,
                             sbase + PROJ_SBOFF + (bcur&1)*SB112, wm, wn, lane);
            if (i + 1 < 18 && bload[(i+1)%3]) bcur++;
        }

#pragma unroll
        for (int mi = 0; mi < 2; mi++) {
#pragma unroll
            for (int hf = 0; hf < 2; hf++) {
                int c = m0 + wm*32 + mi*16 + hf*8 + t4;
                float inv = inv_r[mi*2+hf], sh = sh_r[mi*2+hf];
                float* orow = out + (size_t)t*BCN + ((size_t)b*C_ + c)*N_;
#pragma unroll
                for (int ni = 0; ni < 7; ni++) {
                    int n = n0 + wn*56 + ni*8 + l2;
                    float y0 = d[mi][ni][hf*2+0]*inv + sh;
                    float y1 = d[mi][ni][hf*2+1]*inv + sh;
                    float v0 = v[mi][ni][hf*2+0], v1 = v[mi][ni][hf*2+1];
                    v0 += (y0 - v0)*0.5f; v1 += (y1 - v1)*0.5f;
                    float s0 = (v0 >= 1.0f) ? 1.f : 0.f;
                    float s1 = (v1 >= 1.0f) ? 1.f : 0.f;
                    v[mi][ni][hf*2+0] = (s0 != 0.f) ? 0.f : v0;
                    v[mi][ni][hf*2+1] = (s1 != 0.f) ? 0.f : v1;
                    if (n < N_) {
                        float2 o2; o2.x = s0; o2.y = s1;
                        *(float2*)(orow + n) = o2;
                    }
                }
            }
        }
    }
}

// ---------------- attention (G-factorized, 512 thr, fused LIF 0.5) -> bf16 spikes ----------------
__global__ __launch_bounds__(512, 2) void attn_kernel(const float* __restrict__ policy)
{
    int h = blockIdx.x, b = blockIdx.y;
    int tid = threadIdx.x;

    __shared__ unsigned char Qs[32*196];
    __shared__ unsigned char Ks[32*196];
    __shared__ unsigned char VTs[196*32];
    __shared__ float Gs[32*32];
    __shared__ float Gpart[32*32];
    __shared__ float ps[196];
    __shared__ float dns[196];

    float vlif[16];
#pragma unroll
    for (int d = 0; d < 16; d++) vlif[d] = 0.f;

    for (int t = 0; t < T_; t++) {
        size_t base = (size_t)t*BCN + ((size_t)b*C_ + h*32)*N_;
        for (int i = tid; i < 32*196; i += 512) {
            Qs[i] = g_s[base + i];
            Ks[i] = g_s[(size_t)TBCN + base + i];
            int d = i / 196, m = i - d*196;
            VTs[m*32 + d] = g_s[2*(size_t)TBCN + base + i];
        }
        if (tid < 196)
            ps[tid] = policy[(size_t)(t*B_ + b)*N_ + tid];
        __syncthreads();

        // diag term
        if (tid < 196) {
            int n = tid, dd = 0;
#pragma unroll
            for (int c = 0; c < 32; c++) dd += (int)(Qs[c*196+n] & Ks[c*196+n]);
            dns[n] = (1.0f - ps[n]) * (float)dd;
        }

        // G: thread (c, dg, half); each half sums 98 m's
        {
            int c = tid & 31, dg = (tid >> 5) & 7, half = tid >> 8;
            float g0=0.f,g1=0.f,g2=0.f,g3=0.f;
            const unsigned char* Kc = Ks + c*196;
            const unsigned char* Vb = VTs + dg*4;
            int mbase = half * 98;
#pragma unroll 2
            for (int mm = 0; mm < 98; mm++) {
                int m = mbase + mm;
                float kp = Kc[m] ? ps[m] : 0.0f;
                uchar4 v4 = *(const uchar4*)(Vb + m*32);
                g0 += v4.x ? kp : 0.0f;
                g1 += v4.y ? kp : 0.0f;
                g2 += v4.z ? kp : 0.0f;
                g3 += v4.w ? kp : 0.0f;
            }
            int gi = c*32 + dg*4;
            if (half) {
                Gpart[gi+0]=g0; Gpart[gi+1]=g1; Gpart[gi+2]=g2; Gpart[gi+3]=g3;
            }
            __syncthreads();
            if (!half) {
                Gs[gi+0]=g0+Gpart[gi+0]; Gs[gi+1]=g1+Gpart[gi+1];
                Gs[gi+2]=g2+Gpart[gi+2]; Gs[gi+3]=g3+Gpart[gi+3];
            }
            __syncthreads();
        }

        // Y + fused LIF(0.5): thread (n, dh) owns 16 d's
        if (tid < 392) {
            int n = tid >> 1, dh = tid & 1;
            float acc[16];
#pragma unroll
            for (int d = 0; d < 16; d++) acc[d] = 0.f;
            const unsigned char* Qn = Qs + n;
#pragma unroll
            for (int c = 0; c < 32; c++) {
                float qf = (float)Qn[c*196];
                const float4* Gr = (const float4*)(Gs + c*32 + dh*16);
#pragma unroll
                for (int q4 = 0; q4 < 4; q4++) {
                    float4 g4 = Gr[q4];
                    acc[q4*4+0] += qf * g4.x;
                    acc[q4*4+1] += qf * g4.y;
                    acc[q4*4+2] += qf * g4.z;
                    acc[q4*4+3] += qf * g4.w;
                }
            }
            float dn = dns[n];
            const uchar4* Vn = (const uchar4*)(VTs + n*32 + dh*16);
#pragma unroll
            for (int q4 = 0; q4 < 4; q4++) {
                uchar4 v4 = Vn[q4];
                acc[q4*4+0] += v4.x ? dn : 0.0f;
                acc[q4*4+1] += v4.y ? dn : 0.0f;
                acc[q4*4+2] += v4.z ? dn : 0.0f;
                acc[q4*4+3] += v4.w ? dn : 0.0f;
            }
            __nv_bfloat16* orow = g_sattb + ((size_t)(t*B_ + b)*NP + n)*C_ + h*32 + dh*16;
#pragma unroll
            for (int d = 0; d < 16; d++) {
                float y = 0.25f * acc[d];
                float v = vlif[d];
                v = v + (y - v)*0.5f;
                unsigned char s = (v >= 0.5f) ? 1 : 0;
                orow[d] = __float2bfloat16(s ? 1.0f : 0.0f);
                vlif[d] = s ? 0.f : v;
            }
        } else if (tid >= 392 && tid < 392 + 2*(NP - N_)) {
            int idx = tid - 392;
            int n = N_ + (idx >> 1), dh = idx & 1;
            __nv_bfloat16* orow = g_sattb + ((size_t)(t*B_ + b)*NP + n)*C_ + h*32 + dh*16;
            __nv_bfloat16 z = __float2bfloat16(0.f);
#pragma unroll
            for (int d = 0; d < 16; d++) orow[d] = z;
        }
        __syncthreads();
    }
}

// ---------------- launch ----------------
extern "C" void kernel_launch(void* const* d_in, const int* in_sizes, int n_in,
                              void* d_out, int out_size)
{
    const float* x      = (const float*)d_in[0];
    const float* policy = (const float*)d_in[1];
    const float* qw = (const float*)d_in[2];
    const float* qg = (const float*)d_in[3];
    const float* qb = (const float*)d_in[4];
    const float* qm = (const float*)d_in[5];
    const float* qv = (const float*)d_in[6];
    const float* kw = (const float*)d_in[7];
    const float* kg = (const float*)d_in[8];
    const float* kb = (const float*)d_in[9];
    const float* km = (const float*)d_in[10];
    const float* kv = (const float*)d_in[11];
    const float* vw = (const float*)d_in[12];
    const float* vg = (const float*)d_in[13];
    const float* vb = (const float*)d_in[14];
    const float* vm = (const float*)d_in[15];
    const float* vv = (const float*)d_in[16];
    const float* pw = (const float*)d_in[17];
    const float* pg = (const float*)d_in[18];
    const float* pb = (const float*)d_in[19];
    const float* pm = (const float*)d_in[20];
    const float* pv = (const float*)d_in[21];
    const float* pbias = (const float*)d_in[22];

    cudaFuncSetAttribute(gemm_qkv_mma, cudaFuncAttributeMaxDynamicSharedMemorySize, SMEM_QKV);
    cudaFuncSetAttribute(gemm_proj_mma, cudaFuncAttributeMaxDynamicSharedMemorySize, SMEM_PROJ);

    prep_misc<<<(M3*C_ + 255)/256, 256>>>(qw,kw,vw, pw, qg,qb,qm,qv, kg,kb,km,kv,
                                          vg,vb,vm,vv, pg,pb,pm,pv, pbias);
    prep_x<<<dim3(128, 12, 7), dim3(32, 8)>>>(x);
    gemm_qkv_mma<<<dim3(9, 32), 512, SMEM_QKV>>>();
    attn_kernel<<<dim3(12, 32), 512>>>(policy);
    gemm_proj_mma<<<dim3(3, 2, 32), 256, SMEM_PROJ>>>((float*)d_out);
}

// round 7
// speedup vs baseline: 2.4474x; 1.5149x over previous
#include <cuda_runtime.h>
#include <cuda_fp16.h>
#include <math.h>
#include <stdint.h>

#define T_ 4
#define B_ 32
#define C_ 384
#define N_ 196
#define NP 224
#define BCN (B_*C_*N_)
#define TBCN (T_*BCN)
#define M3 (3*C_)

// ---------------- device scratch ----------------
__device__ unsigned char g_s[3*TBCN];              // qkv spikes u8 [p][t][b][c][n]
__device__ __half g_sattb[(size_t)128*NP*C_];      // attn spikes fp16 [tb][n(224)][c]
__device__ __half g_wq[2][(size_t)M3*C_];          // qkv weight splits (hi/lo fp16)
__device__ __half g_wp[2][(size_t)C_*C_];          // proj weight splits
__device__ __half g_xs[2][(size_t)128*NP*C_];      // x splits [s][tb*224+n][c]
__device__ float g_bninv[4*C_];
__device__ float g_bnshift[4*C_];

// ---------------- helpers ----------------
__device__ __forceinline__ uint32_t smem_u32(const void* p) {
    uint32_t a;
    asm("{ .reg .u64 t; cvta.to.shared.u64 t, %1; cvt.u32.u64 %0, t; }" : "=r"(a) : "l"(p));
    return a;
}
#define CP16(dst, src) asm volatile("cp.async.cg.shared.global [%0], [%1], 16;" :: "r"(dst), "l"(src))
#define CP_COMMIT()    asm volatile("cp.async.commit_group;" ::: "memory")
#define CP_WAIT0()     asm volatile("cp.async.wait_group 0;" ::: "memory")

__device__ __forceinline__ void ldsm_x4(uint32_t& r0, uint32_t& r1, uint32_t& r2, uint32_t& r3, uint32_t a) {
    asm volatile("ldmatrix.sync.aligned.m8n8.x4.shared.b16 {%0,%1,%2,%3}, [%4];"
        : "=r"(r0),"=r"(r1),"=r"(r2),"=r"(r3) : "r"(a));
}
__device__ __forceinline__ void ldsm_x2(uint32_t& r0, uint32_t& r1, uint32_t a) {
    asm volatile("ldmatrix.sync.aligned.m8n8.x2.shared.b16 {%0,%1}, [%2];"
        : "=r"(r0),"=r"(r1) : "r"(a));
}
__device__ __forceinline__ void mma16816(float* d, const uint32_t* a, uint32_t b0, uint32_t b1) {
    asm volatile("mma.sync.aligned.m16n8k16.row.col.f32.f16.f16.f32 "
        "{%0,%1,%2,%3}, {%4,%5,%6,%7}, {%8,%9}, {%0,%1,%2,%3};"
        : "+f"(d[0]),"+f"(d[1]),"+f"(d[2]),"+f"(d[3])
        : "r"(a[0]),"r"(a[1]),"r"(a[2]),"r"(a[3]), "r"(b0),"r"(b1));
}

__device__ __forceinline__ void split2(float x, __half& h, __half& l) {
    h = __float2half_rn(x);
    l = __float2half_rn(x - __half2float(h));
}

// ---------------- prep: weight splits + BN fold ----------------
__global__ void prep_misc(
    const float* __restrict__ qw, const float* __restrict__ kw, const float* __restrict__ vw,
    const float* __restrict__ pw,
    const float* __restrict__ qg, const float* __restrict__ qb, const float* __restrict__ qm, const float* __restrict__ qv,
    const float* __restrict__ kg, const float* __restrict__ kb, const float* __restrict__ km, const float* __restrict__ kvv,
    const float* __restrict__ vg, const float* __restrict__ vb, const float* __restrict__ vm, const float* __restrict__ vvv,
    const float* __restrict__ pg, const float* __restrict__ pb, const float* __restrict__ pm, const float* __restrict__ pv,
    const float* __restrict__ pbias)
{
    int idx = blockIdx.x * blockDim.x + threadIdx.x;
    if (idx < M3*C_) {
        int m = idx / C_, k = idx - m*C_;
        int p = m / C_, o = m - p*C_;
        const float* w = (p==0) ? qw : (p==1) ? kw : vw;
        __half h,l; split2(w[o*C_ + k], h, l);
        g_wq[0][idx] = h; g_wq[1][idx] = l;
    }
    if (idx < C_*C_) {
        __half h,l; split2(pw[idx], h, l);
        g_wp[0][idx] = h; g_wp[1][idx] = l;
    }
    if (idx < 4*C_) {
        int p = idx / C_, c = idx - p*C_;
        const float *G,*Bt,*Mn,*Vr; float bias = 0.f;
        if      (p==0){G=qg;Bt=qb;Mn=qm;Vr=qv;}
        else if (p==1){G=kg;Bt=kb;Mn=km;Vr=kvv;}
        else if (p==2){G=vg;Bt=vb;Mn=vm;Vr=vvv;}
        else          {G=pg;Bt=pb;Mn=pm;Vr=pv; bias=pbias[c];}
        float inv = G[c] / sqrtf(Vr[c] + 1e-5f);
        g_bninv[idx]   = inv;
        g_bnshift[idx] = Bt[c] + (bias - Mn[c]) * inv;
    }
}

// x [t,b,c,n] -> g_xs[s][tb*NP+n][c]  (transpose + split; pad rows zeroed)
__global__ void prep_x(const float* __restrict__ x)
{
    __shared__ float tile[32][33];
    int tb = blockIdx.x;
    int c0 = blockIdx.y * 32;
    int n0 = blockIdx.z * 32;
    int tx = threadIdx.x, ty = threadIdx.y;
#pragma unroll
    for (int r = 0; r < 4; r++) {
        int c = c0 + ty + r*8, n = n0 + tx;
        tile[ty + r*8][tx] = (n < N_) ? x[((size_t)tb*C_ + c)*N_ + n] : 0.f;
    }
    __syncthreads();
#pragma unroll
    for (int r = 0; r < 4; r++) {
        int n = n0 + ty + r*8, c = c0 + tx;
        if (n < NP) {
            __half h,l; split2(tile[tx][ty + r*8], h, l);
            size_t o = ((size_t)tb*NP + n)*C_ + c;
            g_xs[0][o] = h; g_xs[1][o] = l;
        }
    }
}

// ---------------- smem layouts ----------------
#define SA_BYTES 18432              /* 128 rows x 144 B */
#define SB224    32256              /* 224 rows x 144 B */
#define SB112    16128              /* 112 rows x 144 B */
#define QKV_SBOFF (2*SA_BYTES)
#define QKV_SMV   (QKV_SBOFF + 2*SB224)
#define SMEM_QKV  (QKV_SMV + 128*228*4)
#define PROJ_SBOFF (2*SA_BYTES)
#define SMEM_PROJ  (PROJ_SBOFF + 2*SB112)

__device__ __forceinline__ void copy_tile(uint32_t sdst, const __half* src,
                                          int tid, int nthreads, int total) {
    for (int idx = tid; idx < total; idx += nthreads) {
        int row = idx >> 3, cs = idx & 7;
        CP16(sdst + (uint32_t)(row*144 + cs*16), src + (size_t)row*C_ + cs*8);
    }
}

// compute one K=64 chunk: 4 k-steps x (2 A-frags, 7 B-frags, 14 mma)
__device__ __forceinline__ void compute_chunk(
    float d[2][7][4], uint32_t Abase, uint32_t Bbase, int wm, int wn, int lane)
{
    int lr = lane & 15, lc = (lane >> 4) * 16;
    int r8 = lane & 7, hb = ((lane >> 3) & 1) * 16;
    uint32_t arow0 = Abase + (uint32_t)((wm*32 + lr)*144) + lc;
    uint32_t brow0 = Bbase + (uint32_t)((wn*56 + r8)*144) + hb;
#pragma unroll
    for (int ks = 0; ks < 4; ks++) {
        uint32_t a[2][4];
#pragma unroll
        for (int mi = 0; mi < 2; mi++)
            ldsm_x4(a[mi][0],a[mi][1],a[mi][2],a[mi][3], arow0 + mi*16*144 + ks*32);
#pragma unroll
        for (int ni = 0; ni < 7; ni++) {
            uint32_t b0, b1;
            ldsm_x2(b0, b1, brow0 + ni*8*144 + ks*32);
            mma16816(d[0][ni], a[0], b0, b1);
            mma16816(d[1][ni], a[1], b0, b1);
        }
    }
}

// ---------------- qkv GEMM (128x224 tile, 512 thr) + fused LIF -> u8 spikes ----------------
// 3 passes per kc: (Ah,Bh), (Al,Bh), (Ah,Bl)
__global__ __launch_bounds__(512, 1) void gemm_qkv_mma()
{
    extern __shared__ char smem[];
    const uint32_t sbase = smem_u32(smem);
    const int tid = threadIdx.x;
    const int lane = tid & 31, wid = tid >> 5;
    const int wm = wid & 3, wn = wid >> 2;
    const int m0 = blockIdx.x * 128;
    const int b  = blockIdx.y;
    const int p  = m0 / C_, c0 = m0 % C_;

    float* vsm = (float*)(smem + QKV_SMV);
    for (int i = tid; i < 128*228; i += 512) vsm[i] = 0.f;
    __syncthreads();

    const int asel[3]  = {0,1,0};
    const int bsel[3]  = {0,0,1};
    const int bload[3] = {1,0,1};
    const int t4 = lane >> 2, l2 = (lane & 3) * 2;

    for (int t = 0; t < T_; t++) {
        const size_t brow = ((size_t)(t*B_ + b)*NP)*C_;

        float d[2][7][4];
#pragma unroll
        for (int mi=0;mi<2;mi++)
#pragma unroll
            for(int ni=0;ni<7;ni++)
#pragma unroll
                for(int k=0;k<4;k++) d[mi][ni][k]=0.f;

        copy_tile(sbase + 0, g_wq[0] + (size_t)m0*C_, tid, 512, 1024);
        copy_tile(sbase + QKV_SBOFF, g_xs[0] + brow, tid, 512, 1792);
        CP_COMMIT();
        int bcur = 0;

        for (int i = 0; i < 18; i++) {
            CP_WAIT0();
            __syncthreads();
            if (i + 1 < 18) {
                int j1 = (i+1) % 3, kc1 = (i+1) / 3;
                copy_tile(sbase + ((i+1)&1)*SA_BYTES,
                          g_wq[asel[j1]] + (size_t)m0*C_ + kc1*64, tid, 512, 1024);
                if (bload[j1])
                    copy_tile(sbase + QKV_SBOFF + ((bcur+1)&1)*SB224,
                              g_xs[bsel[j1]] + brow + kc1*64, tid, 512, 1792);
                CP_COMMIT();
            }
            compute_chunk(d, sbase + (i&1)*SA_BYTES,
                             sbase + QKV_SBOFF + (bcur&1)*SB224, wm, wn, lane);
            if (i + 1 < 18 && bload[(i+1)%3]) bcur++;
        }

        // epilogue: BN + LIF (state in smem) -> u8 spikes
#pragma unroll
        for (int mi = 0; mi < 2; mi++) {
#pragma unroll
            for (int hf = 0; hf < 2; hf++) {
                int row = wm*32 + mi*16 + hf*8 + t4;
                int m = m0 + row;
                float inv = g_bninv[m], sh = g_bnshift[m];
                unsigned char* orow = g_s + (size_t)p*TBCN + (size_t)t*BCN
                                    + ((size_t)b*C_ + (c0 + row))*N_;
                float* vrow = vsm + row*228;
#pragma unroll
                for (int ni = 0; ni < 7; ni++) {
                    int n = wn*56 + ni*8 + l2;
                    float y0 = d[mi][ni][hf*2+0]*inv + sh;
                    float y1 = d[mi][ni][hf*2+1]*inv + sh;
                    float v0 = vrow[n], v1 = vrow[n+1];
                    v0 += (y0 - v0)*0.5f; v1 += (y1 - v1)*0.5f;
                    unsigned int s0 = (v0 >= 1.0f) ? 1u : 0u;
                    unsigned int s1 = (v1 >= 1.0f) ? 1u : 0u;
                    vrow[n]   = s0 ? 0.f : v0;
                    vrow[n+1] = s1 ? 0.f : v1;
                    if (n < N_)
                        *(unsigned short*)(orow + n) = (unsigned short)(s0 | (s1 << 8));
                }
            }
        }
        __syncthreads();
    }
}

// ---------------- proj GEMM (128x112 tile, 256 thr) + fused final LIF -> fp32 out ----------------
// 2 passes per kc: (Wh,S), (Wl,S)
__global__ __launch_bounds__(256, 1) void gemm_proj_mma(float* __restrict__ out)
{
    extern __shared__ char smem[];
    const uint32_t sbase = smem_u32(smem);
    const int tid = threadIdx.x;
    const int lane = tid & 31, wid = tid >> 5;
    const int wm = wid & 3, wn = wid >> 2;
    const int m0 = blockIdx.x * 128;
    const int n0 = blockIdx.y * 112;
    const int b  = blockIdx.z;

    float inv_r[4], sh_r[4];
#pragma unroll
    for (int q = 0; q < 4; q++) {
        int c = m0 + wm*32 + (q >> 1)*16 + (q & 1)*8 + (lane >> 2);
        inv_r[q] = g_bninv[3*C_ + c]; sh_r[q] = g_bnshift[3*C_ + c];
    }

    float v[2][7][4];
#pragma unroll
    for (int mi=0;mi<2;mi++)
#pragma unroll
        for(int ni=0;ni<7;ni++)
#pragma unroll
            for(int k=0;k<4;k++) v[mi][ni][k]=0.f;

    const int bload[2] = {1,0};
    const int t4 = lane >> 2, l2 = (lane & 3) * 2;

    for (int t = 0; t < T_; t++) {
        const size_t brow = (((size_t)(t*B_ + b))*NP + (size_t)n0)*C_;

        float d[2][7][4];
#pragma unroll
        for (int mi=0;mi<2;mi++)
#pragma unroll
            for(int ni=0;ni<7;ni++)
#pragma unroll
                for(int k=0;k<4;k++) d[mi][ni][k]=0.f;

        copy_tile(sbase + 0, g_wp[0] + (size_t)m0*C_, tid, 256, 1024);
        copy_tile(sbase + PROJ_SBOFF, g_sattb + brow, tid, 256, 896);
        CP_COMMIT();
        int bcur = 0;

        for (int i = 0; i < 12; i++) {
            CP_WAIT0();
            __syncthreads();
            if (i + 1 < 12) {
                int j1 = (i+1) % 2, kc1 = (i+1) / 2;
                copy_tile(sbase + ((i+1)&1)*SA_BYTES,
                          g_wp[j1] + (size_t)m0*C_ + kc1*64, tid, 256, 1024);
                if (bload[j1])
                    copy_tile(sbase + PROJ_SBOFF + ((bcur+1)&1)*SB112,
                              g_sattb + brow + kc1*64, tid, 256, 896);
                CP_COMMIT();
            }
            compute_chunk(d, sbase + (i&1)*SA_BYTES,
                             sbase + PROJ_SBOFF + (bcur&1)*SB112, wm, wn, lane);
            if (i + 1 < 12 && bload[(i+1)%2]) bcur++;
        }

#pragma unroll
        for (int mi = 0; mi < 2; mi++) {
#pragma unroll
            for (int hf = 0; hf < 2; hf++) {
                int c = m0 + wm*32 + mi*16 + hf*8 + t4;
                float inv = inv_r[mi*2+hf], sh = sh_r[mi*2+hf];
                float* orow = out + (size_t)t*BCN + ((size_t)b*C_ + c)*N_;
#pragma unroll
                for (int ni = 0; ni < 7; ni++) {
                    int n = n0 + wn*56 + ni*8 + l2;
                    float y0 = d[mi][ni][hf*2+0]*inv + sh;
                    float y1 = d[mi][ni][hf*2+1]*inv + sh;
                    float v0 = v[mi][ni][hf*2+0], v1 = v[mi][ni][hf*2+1];
                    v0 += (y0 - v0)*0.5f; v1 += (y1 - v1)*0.5f;
                    float s0 = (v0 >= 1.0f) ? 1.f : 0.f;
                    float s1 = (v1 >= 1.0f) ? 1.f : 0.f;
                    v[mi][ni][hf*2+0] = (s0 != 0.f) ? 0.f : v0;
                    v[mi][ni][hf*2+1] = (s1 != 0.f) ? 0.f : v1;
                    if (n < N_) {
                        float2 o2; o2.x = s0; o2.y = s1;
                        *(float2*)(orow + n) = o2;
                    }
                }
            }
        }
    }
}

// ---------------- attention (G-factorized, 512 thr, fused LIF 0.5) -> fp16 spikes ----------------
__global__ __launch_bounds__(512, 2) void attn_kernel(const float* __restrict__ policy)
{
    int h = blockIdx.x, b = blockIdx.y;
    int tid = threadIdx.x;

    __shared__ unsigned char Qs[32*196];
    __shared__ unsigned char Ks[32*196];
    __shared__ unsigned char VTs[196*32];
    __shared__ float Gs[32*32];
    __shared__ float Gpart[32*32];
    __shared__ float ps[196];
    __shared__ float dns[196];

    float vlif[16];
#pragma unroll
    for (int d = 0; d < 16; d++) vlif[d] = 0.f;

    for (int t = 0; t < T_; t++) {
        size_t base = (size_t)t*BCN + ((size_t)b*C_ + h*32)*N_;
        for (int i = tid; i < 32*196; i += 512) {
            Qs[i] = g_s[base + i];
            Ks[i] = g_s[(size_t)TBCN + base + i];
            int d = i / 196, m = i - d*196;
            VTs[m*32 + d] = g_s[2*(size_t)TBCN + base + i];
        }
        if (tid < 196)
            ps[tid] = policy[(size_t)(t*B_ + b)*N_ + tid];
        __syncthreads();

        if (tid < 196) {
            int n = tid, dd = 0;
#pragma unroll
            for (int c = 0; c < 32; c++) dd += (int)(Qs[c*196+n] & Ks[c*196+n]);
            dns[n] = (1.0f - ps[n]) * (float)dd;
        }

        {
            int c = tid & 31, dg = (tid >> 5) & 7, half = tid >> 8;
            float g0=0.f,g1=0.f,g2=0.f,g3=0.f;
            const unsigned char* Kc = Ks + c*196;
            const unsigned char* Vb = VTs + dg*4;
            int mbase = half * 98;
#pragma unroll 2
            for (int mm = 0; mm < 98; mm++) {
                int m = mbase + mm;
                float kp = Kc[m] ? ps[m] : 0.0f;
                uchar4 v4 = *(const uchar4*)(Vb + m*32);
                g0 += v4.x ? kp : 0.0f;
                g1 += v4.y ? kp : 0.0f;
                g2 += v4.z ? kp : 0.0f;
                g3 += v4.w ? kp : 0.0f;
            }
            int gi = c*32 + dg*4;
            if (half) {
                Gpart[gi+0]=g0; Gpart[gi+1]=g1; Gpart[gi+2]=g2; Gpart[gi+3]=g3;
            }
            __syncthreads();
            if (!half) {
                Gs[gi+0]=g0+Gpart[gi+0]; Gs[gi+1]=g1+Gpart[gi+1];
                Gs[gi+2]=g2+Gpart[gi+2]; Gs[gi+3]=g3+Gpart[gi+3];
            }
            __syncthreads();
        }

        if (tid < 392) {
            int n = tid >> 1, dh = tid & 1;
            float acc[16];
#pragma unroll
            for (int d = 0; d < 16; d++) acc[d] = 0.f;
            const unsigned char* Qn = Qs + n;
#pragma unroll
            for (int c = 0; c < 32; c++) {
                float qf = (float)Qn[c*196];
                const float4* Gr = (const float4*)(Gs + c*32 + dh*16);
#pragma unroll
                for (int q4 = 0; q4 < 4; q4++) {
                    float4 g4 = Gr[q4];
                    acc[q4*4+0] += qf * g4.x;
                    acc[q4*4+1] += qf * g4.y;
                    acc[q4*4+2] += qf * g4.z;
                    acc[q4*4+3] += qf * g4.w;
                }
            }
            float dn = dns[n];
            const uchar4* Vn = (const uchar4*)(VTs + n*32 + dh*16);
#pragma unroll
            for (int q4 = 0; q4 < 4; q4++) {
                uchar4 v4 = Vn[q4];
                acc[q4*4+0] += v4.x ? dn : 0.0f;
                acc[q4*4+1] += v4.y ? dn : 0.0f;
                acc[q4*4+2] += v4.z ? dn : 0.0f;
                acc[q4*4+3] += v4.w ? dn : 0.0f;
            }
            __half* orow = g_sattb + ((size_t)(t*B_ + b)*NP + n)*C_ + h*32 + dh*16;
#pragma unroll
            for (int d = 0; d < 16; d++) {
                float y = 0.25f * acc[d];
                float v = vlif[d];
                v = v + (y - v)*0.5f;
                unsigned char s = (v >= 0.5f) ? 1 : 0;
                orow[d] = __float2half(s ? 1.0f : 0.0f);
                vlif[d] = s ? 0.f : v;
            }
        } else if (tid >= 392 && tid < 392 + 2*(NP - N_)) {
            int idx = tid - 392;
            int n = N_ + (idx >> 1), dh = idx & 1;
            __half* orow = g_sattb + ((size_t)(t*B_ + b)*NP + n)*C_ + h*32 + dh*16;
            __half z = __float2half(0.f);
#pragma unroll
            for (int d = 0; d < 16; d++) orow[d] = z;
        }
        __syncthreads();
    }
}

// ---------------- launch ----------------
extern "C" void kernel_launch(void* const* d_in, const int* in_sizes, int n_in,
                              void* d_out, int out_size)
{
    const float* x      = (const float*)d_in[0];
    const float* policy = (const float*)d_in[1];
    const float* qw = (const float*)d_in[2];
    const float* qg = (const float*)d_in[3];
    const float* qb = (const float*)d_in[4];
    const float* qm = (const float*)d_in[5];
    const float* qv = (const float*)d_in[6];
    const float* kw = (const float*)d_in[7];
    const float* kg = (const float*)d_in[8];
    const float* kb = (const float*)d_in[9];
    const float* km = (const float*)d_in[10];
    const float* kv = (const float*)d_in[11];
    const float* vw = (const float*)d_in[12];
    const float* vg = (const float*)d_in[13];
    const float* vb = (const float*)d_in[14];
    const float* vm = (const float*)d_in[15];
    const float* vv = (const float*)d_in[16];
    const float* pw = (const float*)d_in[17];
    const float* pg = (const float*)d_in[18];
    const float* pb = (const float*)d_in[19];
    const float* pm = (const float*)d_in[20];
    const float* pv = (const float*)d_in[21];
    const float* pbias = (const float*)d_in[22];

    cudaFuncSetAttribute(gemm_qkv_mma, cudaFuncAttributeMaxDynamicSharedMemorySize, SMEM_QKV);
    cudaFuncSetAttribute(gemm_proj_mma, cudaFuncAttributeMaxDynamicSharedMemorySize, SMEM_PROJ);

    prep_misc<<<(M3*C_ + 255)/256, 256>>>(qw,kw,vw, pw, qg,qb,qm,qv, kg,kb,km,kv,
                                          vg,vb,vm,vv, pg,pb,pm,pv, pbias);
    prep_x<<<dim3(128, 12, 7), dim3(32, 8)>>>(x);
    gemm_qkv_mma<<<dim3(9, 32), 512, SMEM_QKV>>>();
    attn_kernel<<<dim3(12, 32), 512>>>(policy);
    gemm_proj_mma<<<dim3(3, 2, 32), 256, SMEM_PROJ>>>((float*)d_out);
}